// round 15
// baseline (speedup 1.0000x reference)
#include <cuda_runtime.h>
#include <cuda_fp16.h>
#include <stdint.h>
#include <math.h>

#define Bt 32
#define Ct 684
#define Ht 16
#define Wt 64
#define HWt 1024
#define HIDt 256
#define At 512
#define NPATCH 121
#define KCOMB 805
#define NST 13
#define NPOS 32768
#define NCTA 148
#define ALPHA_OFF (Bt*Ct)
#define ASUM_OFF  (Bt*Ct + Bt*HWt)

// dynamic smem: Xbuf[2]@0 (32768) | Wbuf[2]@32768 (65536) | stg[3]@98304 (3*33792) | asum@199680 (4096)
#define XB  0
#define WB  32768
#define STG 98304
#define STGB 33792
#define ASM 199680
#define SMEM_SZ 203776
#define XT 16384
#define WT 32768
#define STGP 132
#define NTILE 512

// ---------------- device scratch ----------------
__device__ __align__(1024) unsigned char g_W[(size_t)2 * NST * WT];
__device__ float g_Weff[At * NPATCH];
__device__ float g_query[Bt * At];
__device__ float g_Epart[2 * NPOS];
__device__ int g_cnt[2];

// ---------------- helpers ----------------
__device__ __forceinline__ uint32_t smem_u32(const void* p) {
    uint32_t a;
    asm("{ .reg .u64 t; cvta.to.shared.u64 t, %1; cvt.u32.u64 %0, t; }" : "=r"(a) : "l"(p));
    return a;
}
__device__ __forceinline__ void mb_init(uint32_t a, uint32_t c) {
    asm volatile("mbarrier.init.shared.b64 [%0], %1;" :: "r"(a), "r"(c) : "memory");
}
__device__ __forceinline__ void mb_arrive(uint32_t a) {
    asm volatile("mbarrier.arrive.shared.b64 _, [%0];" :: "r"(a) : "memory");
}
__device__ __forceinline__ void mb_tx(uint32_t a, uint32_t bytes) {
    asm volatile("mbarrier.arrive.expect_tx.shared.b64 _, [%0], %1;" :: "r"(a), "r"(bytes) : "memory");
}
__device__ __forceinline__ void mb_wait(uint32_t a, uint32_t par) {
    uint32_t d = 0;
    while (!d)
        asm volatile("{ .reg .pred p; mbarrier.try_wait.parity.acquire.cta.shared::cta.b64 p,[%1],%2,0x989680; selp.b32 %0,1,0,p; }"
                     : "=r"(d) : "r"(a), "r"(par) : "memory");
}
__device__ __forceinline__ void blkcp(uint32_t dst, const void* src, uint32_t bytes, uint32_t mbar) {
    asm volatile("cp.async.bulk.shared::cta.global.mbarrier::complete_tx::bytes [%0], [%1], %2, [%3];"
                 :: "r"(dst), "l"(src), "r"(bytes), "r"(mbar) : "memory");
}
#define BARS(id, n) asm volatile("bar.sync %0, %1;" :: "r"(id), "r"(n) : "memory")
#define LDMX4(r0,r1,r2,r3,addr) \
    asm volatile("ldmatrix.sync.aligned.m8n8.x4.shared.b16 {%0,%1,%2,%3}, [%4];" \
                 : "=r"(r0),"=r"(r1),"=r"(r2),"=r"(r3) : "r"(addr))
#define MMA(d,a,b) \
    asm volatile("mma.sync.aligned.m16n8k16.row.col.f32.f16.f16.f32 " \
                 "{%0,%1,%2,%3},{%4,%5,%6,%7},{%8,%9},{%0,%1,%2,%3};" \
                 : "+f"(d[0]),"+f"(d[1]),"+f"(d[2]),"+f"(d[3]) \
                 : "r"(a[0]),"r"(a[1]),"r"(a[2]),"r"(a[3]),"r"(b[0]),"r"(b[1]))

__device__ __forceinline__ uint32_t h2u(float v0, float v1) {
    __half2 h = __floats2half2_rn(v0, v1);
    return *(uint32_t*)&h;
}
__device__ __forceinline__ float ftanh(float x) {
    float e = __expf(2.0f * x);
    return 1.0f - __fdividef(2.0f, e + 1.0f);
}
__device__ __forceinline__ void gridbar(int ph) {
    __syncthreads();
    if (threadIdx.x == 0) {
        __threadfence();
        atomicAdd(&g_cnt[ph], 1);
        while (atomicAdd(&g_cnt[ph], 0) < NCTA) { }
        __threadfence();
    }
    __syncthreads();
}

// ---------------- prep: merged weff (y=0) + query (y=1) ----------------
__global__ void k_small(const float* __restrict__ Waw, const float* __restrict__ Wac,
                        const float* __restrict__ hidden, const float* __restrict__ Wh,
                        const float* __restrict__ bh, const float* __restrict__ bec) {
    if (blockIdx.y == 0) {
        int a = blockIdx.x, j = threadIdx.x;
        if (j >= NPATCH) return;
        float s = 0.f;
        for (int c = 0; c < At; ++c) s = fmaf(Waw[a * At + c], Wac[c * NPATCH + j], s);
        g_Weff[a * NPATCH + j] = s;
    } else {
        int b = blockIdx.x, tid = threadIdx.x;
        if (b >= Bt) return;
        __shared__ float h[HIDt];
        for (int k = tid; k < HIDt; k += 128) h[k] = hidden[b * HIDt + k];
        __syncthreads();
        for (int a = tid; a < At; a += 128) {
            const float* wr = Wh + a * HIDt;
            float s = 0.f;
            #pragma unroll 8
            for (int k = 0; k < HIDt; ++k) s = fmaf(wr[k], h[k], s);
            g_query[b * At + a] = s + bh[a] + bec[a];
        }
    }
}

// ---------------- prep: W tiles [ag][s] 256a x 64k fp16, SW128-swizzled ----------------
__global__ void k_wpack(const float* __restrict__ Wec) {
    __shared__ float sm[64][129];
    const int s = blockIdx.x, ag = blockIdx.y, tid = threadIdx.x;
    const int w = tid >> 5, lane = tid & 31;
    #pragma unroll 4
    for (int i = 0; i < 32; ++i) {
        int kk = lane + (i & 1) * 32;
        int a = w + (i >> 1) * 8;
        int k = s * 64 + kk, aa = ag * 128 + a;
        float v = 0.f;
        if (k < Ct) v = Wec[aa * Ct + k];
        else if (k < KCOMB) v = g_Weff[aa * NPATCH + (k - Ct)];
        sm[kk][a] = v;
    }
    __syncthreads();
    unsigned char* tile = g_W + ((size_t)((ag >> 1) * NST + s) << 15);
    const int rbase = (ag & 1) * 128;
    #pragma unroll
    for (int i = 0; i < 4; ++i) {
        int idx = i * 256 + tid;
        int r = idx >> 3, ch = idx & 7;
        uint32_t hv[4];
        #pragma unroll
        for (int j = 0; j < 4; ++j)
            hv[j] = h2u(sm[ch * 8 + 2 * j][r], sm[ch * 8 + 2 * j + 1][r]);
        int r2 = rbase + r;
        uint32_t off = r2 * 128 + ((ch ^ (r2 & 7)) << 4);
        *(uint4*)(tile + off) = make_uint4(hv[0], hv[1], hv[2], hv[3]);
    }
}

__global__ void k_zero() {
    if (threadIdx.x < 2) g_cnt[threadIdx.x] = 0;
}

// ---------------- main: persistent megakernel, bulk-staged X + staggered convert ----------------
__global__ __launch_bounds__(256, 1)
void k_mma(const float* __restrict__ cnn, const float* __restrict__ asum,
           const float* __restrict__ mask, const float* __restrict__ Wv,
           const float* __restrict__ bv, float* __restrict__ out) {
    extern __shared__ char dsm[];
    __shared__ float qs[256], ws[256], esm[512];
    __shared__ __align__(8) uint64_t mbars[5];   // W full[2], stg full[3]
    const uint32_t sb = smem_u32(dsm);
    const uint32_t mbF = smem_u32(&mbars[0]);
    const uint32_t mbS = mbF + 16;
    float* asm_s = (float*)(dsm + ASM);
    const int tid = threadIdx.x, lane = tid & 31, w = tid >> 5;
    const int wm = w >> 2, wn = w & 3;
    const int half = w >> 2;
    const int htid = tid & 127;

    if (tid == 0) {
        mb_init(mbF, 1); mb_init(mbF + 8, 1);
        mb_init(mbS, 1); mb_init(mbS + 8, 1); mb_init(mbS + 16, 1);
    }
    __syncthreads();

    int tiles[4], ntiles = 0;
    for (int t = blockIdx.x; t < NTILE; t += NCTA) tiles[ntiles++] = t;
    const int total = ntiles * NST;

    // bulk-issue fp32 cnn rows of global-stage g into stg[g % 3] (tid 0 only)
    auto stgIssue = [&](int g) {
        int ti2 = g / NST, s2 = g - ti2 * NST, bx = tiles[ti2] >> 1;
        int b2 = bx >> 3, pos0b = (bx & 7) * 128;
        int k0 = s2 * 64;
        int nrows = (k0 < Ct) ? ((Ct - k0 < 64) ? (Ct - k0) : 64) : 0;
        uint32_t bar = mbS + (g % 3) * 8;
        uint32_t dstb = sb + STG + (g % 3) * STGB;
        if (nrows > 0) {
            mb_tx(bar, (uint32_t)nrows * 512u);
            const float* src = cnn + ((size_t)b2 * Ct + k0) * HWt + pos0b;
            for (int r = 0; r < nrows; ++r)
                blkcp(dstb + r * (STGP * 4), src + (size_t)r * HWt, 512u, bar);
        } else {
            mb_arrive(bar);
        }
    };

    // convert stg[g%3] (+im2col) -> swizzled fp16 tile Xbuf[g&1]; subset: iters x stride
    auto convert = [&](int g, int lid, int iters, int stride) {
        int ti2 = g / NST, s2 = g - ti2 * NST, bx = tiles[ti2] >> 1;
        int pos0b = (bx & 7) * 128;
        float* stgf = (float*)(dsm + STG + (g % 3) * STGB);
        char* dx = dsm + XB + (g & 1) * XT;
        const int k0 = s2 * 64;
        if (k0 + 63 < Ct) {
            for (int i = 0; i < iters; ++i) {
                int idx = i * stride + lid;
                int r = idx & 127, ch = idx >> 7;
                uint32_t hv[4];
                #pragma unroll
                for (int j = 0; j < 4; ++j)
                    hv[j] = h2u(stgf[(ch * 8 + 2 * j) * STGP + r],
                                stgf[(ch * 8 + 2 * j + 1) * STGP + r]);
                uint32_t off = r * 128 + ((ch ^ (r & 7)) << 4);
                *(uint4*)(dx + off) = make_uint4(hv[0], hv[1], hv[2], hv[3]);
            }
        } else {
            for (int i = 0; i < iters; ++i) {
                int idx = i * stride + lid;
                int r = idx & 127, ch = idx >> 7;
                float v[8];
                #pragma unroll
                for (int jj = 0; jj < 8; ++jj) {
                    int kk = ch * 8 + jj, k = k0 + kk;
                    float x = 0.f;
                    if (k < Ct) {
                        x = stgf[kk * STGP + r];
                    } else if (k < KCOMB) {
                        int j = k - Ct;
                        int pos = pos0b + r;
                        int hh = (pos >> 6) + j / 11 - 5;
                        int ww = (pos & 63) + j % 11 - 5;
                        if (hh >= 0 && hh < Ht && ww >= 0 && ww < Wt) x = asm_s[hh * Wt + ww];
                    }
                    v[jj] = x;
                }
                uint32_t hv[4];
                #pragma unroll
                for (int j = 0; j < 4; ++j) hv[j] = h2u(v[2 * j], v[2 * j + 1]);
                uint32_t off = r * 128 + ((ch ^ (r & 7)) << 4);
                *(uint4*)(dx + off) = make_uint4(hv[0], hv[1], hv[2], hv[3]);
            }
        }
    };

    // ---- prologue: W(0), staging(0,1), asum, convert(0) ----
    {
        int by0 = tiles[0] & 1, b0 = (tiles[0] >> 1) >> 3;
        if (tid == 0) {
            mb_tx(mbF, WT);
            blkcp(sb + WB, g_W + ((size_t)(by0 * NST) << 15), WT, mbF);
            stgIssue(0);
            if (total > 1) stgIssue(1);
        }
        for (int i = tid; i < HWt; i += 256) asm_s[i] = asum[b0 * HWt + i];
        __syncthreads();
        mb_wait(mbS, 0);
        convert(0, tid, 4, 256);
        __syncthreads();
    }

    float acc[4][8][4];
    #pragma unroll
    for (int mt = 0; mt < 4; ++mt)
        #pragma unroll
        for (int nt = 0; nt < 8; ++nt)
            #pragma unroll
            for (int r = 0; r < 4; ++r) acc[mt][nt][r] = 0.f;

    int ti = 0, s = 0;
    for (int g = 0; g < total; ++g) {
        // staging issue for g+2 into stg[(g+2)%3]; prior reader convert(g-1) joined 2 syncs ago
        if (tid == 0 && g + 2 < total) stgIssue(g + 2);
        __syncthreads();   // joins MMA(g-1) of ALL warps; Wbuf/Xbuf[(g+1)&1] free
        // W issue for g+1 AFTER the sync: previous reader (MMA(g-1)) of Wbuf[(g+1)&1] is joined
        if (tid == 0 && g + 1 < total) {
            int nti = (g + 1) / NST, ns2 = (g + 1) - nti * NST, nby = tiles[nti] & 1;
            uint32_t fb = mbF + ((g + 1) & 1) * 8;
            mb_tx(fb, WT);
            blkcp(sb + WB + ((g + 1) & 1) * WT, g_W + ((size_t)(nby * NST + ns2) << 15), WT, fb);
        }
        // staggered convert: one half converts g+1 (waits its staging barrier), other half -> MMA(g)
        if (g + 1 < total && half == ((g + 1) & 1)) {
            mb_wait(mbS + ((g + 1) % 3) * 8, ((g + 1) / 3) & 1);
            convert(g + 1, htid, 8, 128);
        }
        // MMA stage g
        mb_wait(mbF + (g & 1) * 8, (g >> 1) & 1);
        {
            const uint32_t xb = sb + XB + (g & 1) * XT;
            const uint32_t wb = sb + WB + (g & 1) * WT;
            #pragma unroll
            for (int ks = 0; ks < 4; ++ks) {
                uint32_t bf[8][2];
                const int browb = wn * 64 + (lane & 7) + ((lane >> 4) & 1) * 8;
                const int bc = 2 * ks + ((lane >> 3) & 1);
                #pragma unroll
                for (int np = 0; np < 4; ++np) {
                    int r = browb + np * 16;
                    uint32_t boff = r * 128 + ((bc ^ (r & 7)) << 4);
                    LDMX4(bf[np*2][0], bf[np*2][1], bf[np*2+1][0], bf[np*2+1][1], wb + boff);
                }
                const int arow = wm * 64 + (lane & 15);
                const int ac = 2 * ks + (lane >> 4);
                #pragma unroll
                for (int mt = 0; mt < 4; ++mt) {
                    int r = arow + mt * 16;
                    uint32_t aoff = r * 128 + ((ac ^ (r & 7)) << 4);
                    uint32_t af[4];
                    LDMX4(af[0], af[1], af[2], af[3], xb + aoff);
                    #pragma unroll
                    for (int nt = 0; nt < 8; ++nt)
                        MMA(acc[mt][nt], af, bf[nt]);
                }
            }
        }

        if (++s == NST) {
            // ---- epilogue for tile ti ----
            const int bx = tiles[ti] >> 1, by = tiles[ti] & 1;
            const int pos0 = bx * 128, a0 = by * 256, b = bx >> 3;
            __syncthreads();
            qs[tid] = g_query[b * At + a0 + tid];
            ws[tid] = Wv[a0 + tid];
            __syncthreads();
            #pragma unroll
            for (int mt = 0; mt < 4; ++mt) {
                float er0 = 0.f, er1 = 0.f;
                #pragma unroll
                for (int nt = 0; nt < 8; ++nt) {
                    int col = wn * 64 + nt * 8 + (lane & 3) * 2;
                    float q0 = qs[col], q1 = qs[col + 1];
                    float w0 = ws[col], w1 = ws[col + 1];
                    er0 = fmaf(w0, ftanh(acc[mt][nt][0] + q0), er0);
                    er0 = fmaf(w1, ftanh(acc[mt][nt][1] + q1), er0);
                    er1 = fmaf(w0, ftanh(acc[mt][nt][2] + q0), er1);
                    er1 = fmaf(w1, ftanh(acc[mt][nt][3] + q1), er1);
                }
                er0 += __shfl_xor_sync(0xffffffffu, er0, 1);
                er0 += __shfl_xor_sync(0xffffffffu, er0, 2);
                er1 += __shfl_xor_sync(0xffffffffu, er1, 1);
                er1 += __shfl_xor_sync(0xffffffffu, er1, 2);
                if ((lane & 3) == 0) {
                    int r = wm * 64 + mt * 16 + (lane >> 2);
                    esm[r * 4 + wn] = er0;
                    esm[(r + 8) * 4 + wn] = er1;
                }
            }
            __syncthreads();
            if (tid < 128)
                g_Epart[by * NPOS + pos0 + tid] =
                    esm[tid * 4] + esm[tid * 4 + 1] + esm[tid * 4 + 2] + esm[tid * 4 + 3];
            #pragma unroll
            for (int mt = 0; mt < 4; ++mt)
                #pragma unroll
                for (int nt = 0; nt < 8; ++nt)
                    #pragma unroll
                    for (int r = 0; r < 4; ++r) acc[mt][nt][r] = 0.f;
            if (ti + 1 < ntiles) {
                int nb = (tiles[ti + 1] >> 1) >> 3;
                for (int i = tid; i < HWt; i += 256) asm_s[i] = asum[nb * HWt + i];
            }
            s = 0; ++ti;
        }
    }

    // ==== all Epart written ====
    gridbar(0);

    // softmax per batch (CTAs 0-31); per-batch max (normalization-invariant)
    if (blockIdx.x < Bt) {
        const int b = blockIdx.x;
        float* exs = (float*)dsm;
        float bvv = bv[0];
        float ev[4], m = -1e30f;
        #pragma unroll
        for (int i = 0; i < 4; ++i) {
            int p = tid + i * 256;
            float e = bvv + g_Epart[b * HWt + p] + g_Epart[NPOS + b * HWt + p];
            ev[i] = e; m = fmaxf(m, e);
        }
        esm[tid] = m; __syncthreads();
        for (int s2 = 128; s2 > 0; s2 >>= 1) { if (tid < s2) esm[tid] = fmaxf(esm[tid], esm[tid + s2]); __syncthreads(); }
        m = esm[0];
        __syncthreads();
        float ls = 0.f;
        #pragma unroll
        for (int i = 0; i < 4; ++i) {
            int p = tid + i * 256;
            float v = expf(ev[i] - m) * mask[b * HWt + p];
            exs[p] = v; ls += v;
        }
        esm[tid] = ls; __syncthreads();
        for (int s2 = 128; s2 > 0; s2 >>= 1) { if (tid < s2) esm[tid] += esm[tid + s2]; __syncthreads(); }
        float inv = 1.f / (esm[0] + 1e-10f);
        #pragma unroll
        for (int i = 0; i < 4; ++i) {
            int p = tid + i * 256;
            float al = exs[p] * inv;
            out[ALPHA_OFF + b * HWt + p] = al;
            out[ASUM_OFF + b * HWt + p] = al + asum[b * HWt + p];
        }
    }

    gridbar(1);

    // context: full chip, 2 c-rows per block-iteration (alpha hot in L2)
    {
        const int cr = tid >> 7, l = tid & 127;
        const int wq = (tid >> 5) & 3;
        for (int idx = blockIdx.x; idx < (Ct / 2) * Bt; idx += NCTA) {
            int b = idx / (Ct / 2);
            int cp = idx - b * (Ct / 2);
            int c = cp * 2 + cr;
            const float4* f = (const float4*)(cnn + (size_t)(b * Ct + c) * HWt);
            const float4* al = (const float4*)(out + ALPHA_OFF + b * HWt);
            float sdot = 0.f;
            #pragma unroll
            for (int i = 0; i < 2; ++i) {
                float4 a4 = al[l + i * 128], f4 = f[l + i * 128];
                sdot += a4.x * f4.x + a4.y * f4.y + a4.z * f4.z + a4.w * f4.w;
            }
            #pragma unroll
            for (int o = 16; o > 0; o >>= 1) sdot += __shfl_xor_sync(0xffffffffu, sdot, o);
            if (lane == 0) esm[cr * 4 + wq] = sdot;
            BARS(3 + cr, 128);
            if (l == 0)
                out[b * Ct + c] = esm[cr * 4] + esm[cr * 4 + 1] + esm[cr * 4 + 2] + esm[cr * 4 + 3];
            BARS(3 + cr, 128);
        }
    }
}

// ---------------- launch ----------------
extern "C" void kernel_launch(void* const* d_in, const int* in_sizes, int n_in,
                              void* d_out, int out_size) {
    const float* cnn    = (const float*)d_in[0];
    const float* hidden = (const float*)d_in[1];
    const float* asum   = (const float*)d_in[2];
    const float* mask   = (const float*)d_in[3];
    const float* Wh     = (const float*)d_in[4];
    const float* bh     = (const float*)d_in[5];
    const float* Wec    = (const float*)d_in[6];
    const float* bec    = (const float*)d_in[7];
    const float* Wac    = (const float*)d_in[8];
    const float* Waw    = (const float*)d_in[9];
    const float* Wv     = (const float*)d_in[10];
    const float* bv     = (const float*)d_in[11];
    float* out = (float*)d_out;

    cudaFuncSetAttribute(k_mma, cudaFuncAttributeMaxDynamicSharedMemorySize, SMEM_SZ);

    k_small<<<dim3(At, 2), 128>>>(Waw, Wac, hidden, Wh, bh, bec);   // 1
    k_wpack<<<dim3(NST, 4), 256>>>(Wec);                            // 2
    k_zero<<<1, 32>>>();                                            // 3
    k_mma<<<NCTA, 256, SMEM_SZ>>>(cnn, asum, mask, Wv, bv, out);    // 4 <- ncu slot
}

// round 16
// speedup vs baseline: 1.2305x; 1.2305x over previous
#include <cuda_runtime.h>
#include <cuda_fp16.h>
#include <stdint.h>
#include <math.h>

#define Bt 32
#define Ct 684
#define Ht 16
#define Wt 64
#define HWt 1024
#define HIDt 256
#define At 512
#define NPATCH 121
#define KCOMB 805
#define NST 13
#define NPOS 32768
#define NCTA 148
#define NPJ 160                 // padded patch rows (121 real + zeros)
#define ALPHA_OFF (Bt*Ct)
#define ASUM_OFF  (Bt*Ct + Bt*HWt)

// dynamic smem: Wbuf[2]@0 (65536) | stg[3]@65536 (3*17408 = 52224)
#define WB  0
#define STG 65536
#define STGB 17408              // 64 rows * 272 B
#define SMEM_SZ 117760
#define WT 32768
#define NTILE 512

// ---------------- device scratch ----------------
__device__ __align__(1024) unsigned char g_W[(size_t)2 * NST * WT];
__device__ __align__(16) __half g_cnn16[(size_t)Bt * Ct * HWt];   // 44.8 MB
__device__ __align__(16) __half g_P[(size_t)Bt * NPJ * HWt];      // 10.5 MB (zero-padded)
__device__ float g_Weff[At * NPATCH];
__device__ float g_query[Bt * At];
__device__ float g_Epart[2 * NPOS];
__device__ int g_cnt[2];

// ---------------- helpers ----------------
__device__ __forceinline__ uint32_t smem_u32(const void* p) {
    uint32_t a;
    asm("{ .reg .u64 t; cvta.to.shared.u64 t, %1; cvt.u32.u64 %0, t; }" : "=r"(a) : "l"(p));
    return a;
}
__device__ __forceinline__ void mb_init(uint32_t a, uint32_t c) {
    asm volatile("mbarrier.init.shared.b64 [%0], %1;" :: "r"(a), "r"(c) : "memory");
}
__device__ __forceinline__ void mb_tx(uint32_t a, uint32_t bytes) {
    asm volatile("mbarrier.arrive.expect_tx.shared.b64 _, [%0], %1;" :: "r"(a), "r"(bytes) : "memory");
}
__device__ __forceinline__ void mb_wait(uint32_t a, uint32_t par) {
    uint32_t d = 0;
    while (!d)
        asm volatile("{ .reg .pred p; mbarrier.try_wait.parity.acquire.cta.shared::cta.b64 p,[%1],%2,0x989680; selp.b32 %0,1,0,p; }"
                     : "=r"(d) : "r"(a), "r"(par) : "memory");
}
__device__ __forceinline__ void blkcp(uint32_t dst, const void* src, uint32_t bytes, uint32_t mbar) {
    asm volatile("cp.async.bulk.shared::cta.global.mbarrier::complete_tx::bytes [%0], [%1], %2, [%3];"
                 :: "r"(dst), "l"(src), "r"(bytes), "r"(mbar) : "memory");
}
__device__ __forceinline__ void cpa16(uint32_t dst, const void* src) {
    asm volatile("cp.async.cg.shared.global [%0], [%1], 16;" :: "r"(dst), "l"(src));
}
#define BARS(id, n) asm volatile("bar.sync %0, %1;" :: "r"(id), "r"(n) : "memory")
#define LDMX4(r0,r1,r2,r3,addr) \
    asm volatile("ldmatrix.sync.aligned.m8n8.x4.shared.b16 {%0,%1,%2,%3}, [%4];" \
                 : "=r"(r0),"=r"(r1),"=r"(r2),"=r"(r3) : "r"(addr))
#define LDMX4T(r0,r1,r2,r3,addr) \
    asm volatile("ldmatrix.sync.aligned.m8n8.x4.trans.shared.b16 {%0,%1,%2,%3}, [%4];" \
                 : "=r"(r0),"=r"(r1),"=r"(r2),"=r"(r3) : "r"(addr))
#define MMA(d,a,b) \
    asm volatile("mma.sync.aligned.m16n8k16.row.col.f32.f16.f16.f32 " \
                 "{%0,%1,%2,%3},{%4,%5,%6,%7},{%8,%9},{%0,%1,%2,%3};" \
                 : "+f"(d[0]),"+f"(d[1]),"+f"(d[2]),"+f"(d[3]) \
                 : "r"(a[0]),"r"(a[1]),"r"(a[2]),"r"(a[3]),"r"(b[0]),"r"(b[1]))

__device__ __forceinline__ uint32_t h2u(float v0, float v1) {
    __half2 h = __floats2half2_rn(v0, v1);
    return *(uint32_t*)&h;
}
__device__ __forceinline__ float ftanh(float x) {
    float e = __expf(2.0f * x);
    return 1.0f - __fdividef(2.0f, e + 1.0f);
}
__device__ __forceinline__ void gridbar(int ph) {
    __syncthreads();
    if (threadIdx.x == 0) {
        __threadfence();
        atomicAdd(&g_cnt[ph], 1);
        while (atomicAdd(&g_cnt[ph], 0) < NCTA) { }
        __threadfence();
    }
    __syncthreads();
}

// ---------------- prep: merged weff (y=0, also zeroes counters) + query (y=1) ----------------
__global__ void k_small(const float* __restrict__ Waw, const float* __restrict__ Wac,
                        const float* __restrict__ hidden, const float* __restrict__ Wh,
                        const float* __restrict__ bh, const float* __restrict__ bec) {
    if (blockIdx.y == 0) {
        int a = blockIdx.x, j = threadIdx.x;
        if (a == 0 && (j == 121 || j == 122)) g_cnt[j - 121] = 0;
        if (j >= NPATCH) return;
        float s = 0.f;
        for (int c = 0; c < At; ++c) s = fmaf(Waw[a * At + c], Wac[c * NPATCH + j], s);
        g_Weff[a * NPATCH + j] = s;
    } else {
        int b = blockIdx.x, tid = threadIdx.x;
        if (b >= Bt) return;
        __shared__ float h[HIDt];
        for (int k = tid; k < HIDt; k += 128) h[k] = hidden[b * HIDt + k];
        __syncthreads();
        for (int a = tid; a < At; a += 128) {
            const float* wr = Wh + a * HIDt;
            float s = 0.f;
            #pragma unroll 8
            for (int k = 0; k < HIDt; ++k) s = fmaf(wr[k], h[k], s);
            g_query[b * At + a] = s + bh[a] + bec[a];
        }
    }
}

// ---------------- prep: W tiles [ag][s] 256a x 64k fp16, SW128-swizzled ----------------
__global__ void k_wpack(const float* __restrict__ Wec) {
    __shared__ float sm[64][129];
    const int s = blockIdx.x, ag = blockIdx.y, tid = threadIdx.x;
    const int w = tid >> 5, lane = tid & 31;
    #pragma unroll 4
    for (int i = 0; i < 32; ++i) {
        int kk = lane + (i & 1) * 32;
        int a = w + (i >> 1) * 8;
        int k = s * 64 + kk, aa = ag * 128 + a;
        float v = 0.f;
        if (k < Ct) v = Wec[aa * Ct + k];
        else if (k < KCOMB) v = g_Weff[aa * NPATCH + (k - Ct)];
        sm[kk][a] = v;
    }
    __syncthreads();
    unsigned char* tile = g_W + ((size_t)((ag >> 1) * NST + s) << 15);
    const int rbase = (ag & 1) * 128;
    #pragma unroll
    for (int i = 0; i < 4; ++i) {
        int idx = i * 256 + tid;
        int r = idx >> 3, ch = idx & 7;
        uint32_t hv[4];
        #pragma unroll
        for (int j = 0; j < 4; ++j)
            hv[j] = h2u(sm[ch * 8 + 2 * j][r], sm[ch * 8 + 2 * j + 1][r]);
        int r2 = rbase + r;
        uint32_t off = r2 * 128 + ((ch ^ (r2 & 7)) << 4);
        *(uint4*)(tile + off) = make_uint4(hv[0], hv[1], hv[2], hv[3]);
    }
}

// ---------------- prep: streaming fp32->fp16 cnn convert (y=0) + fp16 patches (y=1) ----------------
__global__ void k_xconv(const float* __restrict__ cnn, const float* __restrict__ asum) {
    if (blockIdx.y == 0) {
        size_t idx = (size_t)blockIdx.x * 256 + threadIdx.x;
        size_t base = idx * 4;               // grid sized exactly: 21888*256*4 = 22413312
        float4 v = *(const float4*)(cnn + base);
        __half2 h0 = __floats2half2_rn(v.x, v.y);
        __half2 h1 = __floats2half2_rn(v.z, v.w);
        uint2 u;
        u.x = *(uint32_t*)&h0;
        u.y = *(uint32_t*)&h1;
        *(uint2*)(g_cnn16 + base) = u;
    } else {
        int idx = blockIdx.x * 256 + threadIdx.x;
        if (idx >= Bt * NPJ * HWt) return;
        int b = idx / (NPJ * HWt), r2 = idx % (NPJ * HWt);
        int j = r2 >> 10, pos = r2 & 1023;
        float v = 0.f;
        if (j < NPATCH) {
            int hh = (pos >> 6) + j / 11 - 5;
            int ww = (pos & 63) + j % 11 - 5;
            if (hh >= 0 && hh < Ht && ww >= 0 && ww < Wt) v = asum[b * HWt + hh * Wt + ww];
        }
        g_P[idx] = __float2half(v);
    }
}

// ---------------- main: persistent megakernel, direct fp16 staging + ldmatrix.trans A ----------------
__global__ __launch_bounds__(256, 1)
void k_mma(const float* __restrict__ asum, const float* __restrict__ mask,
           const float* __restrict__ Wv, const float* __restrict__ bv,
           const float* __restrict__ cnn, float* __restrict__ out) {
    extern __shared__ char dsm[];
    __shared__ float qs[256], ws[256], esm[512];
    __shared__ __align__(8) uint64_t mbars[2];
    const uint32_t sb = smem_u32(dsm);
    const uint32_t mbF = smem_u32(&mbars[0]);
    const int tid = threadIdx.x, lane = tid & 31, w = tid >> 5;
    const int wm = w >> 2, wn = w & 3;

    if (tid == 0) { mb_init(mbF, 1); mb_init(mbF + 8, 1); }
    __syncthreads();

    int tiles[4], ntiles = 0;
    for (int t = blockIdx.x; t < NTILE; t += NCTA) tiles[ntiles++] = t;
    const int total = ntiles * NST;

    // cp.async fp16 k-rows of stage g into stg[g % 3] (272 B padded rows)
    auto cpaX = [&](int g) {
        int ti2 = g / NST, s2 = g - ti2 * NST, bx = tiles[ti2] >> 1;
        int b2 = bx >> 3, pos0b = (bx & 7) * 128;
        int k0 = s2 * 64;
        uint32_t dstb = sb + STG + (g % 3) * STGB;
        const __half* c16 = g_cnn16 + (size_t)b2 * Ct * HWt + pos0b;
        const __half* pp  = g_P + (size_t)b2 * NPJ * HWt + pos0b;
        #pragma unroll
        for (int i = 0; i < 4; ++i) {
            int id = i * 256 + tid;
            int row = id >> 4, c = id & 15;
            int k = k0 + row;
            const __half* src = (k < Ct) ? (c16 + (size_t)k * HWt) : (pp + (size_t)(k - Ct) * HWt);
            cpa16(dstb + row * 272 + c * 16, (const char*)src + c * 16);
        }
    };

    // ---- prologue: W(0), staging(0,1) ----
    {
        int by0 = tiles[0] & 1;
        if (tid == 0) {
            mb_tx(mbF, WT);
            blkcp(sb + WB, g_W + ((size_t)(by0 * NST) << 15), WT, mbF);
        }
        cpaX(0);
        asm volatile("cp.async.commit_group;" ::: "memory");
        if (total > 1) cpaX(1);
        asm volatile("cp.async.commit_group;" ::: "memory");
    }

    float acc[4][8][4];
    #pragma unroll
    for (int mt = 0; mt < 4; ++mt)
        #pragma unroll
        for (int nt = 0; nt < 8; ++nt)
            #pragma unroll
            for (int r = 0; r < 4; ++r) acc[mt][nt][r] = 0.f;

    int ti = 0, s = 0;
    for (int g = 0; g < total; ++g) {
        asm volatile("cp.async.wait_group 1;" ::: "memory");   // staging(g) complete
        __syncthreads();   // joins MMA(g-1) of ALL warps; staging(g) visible; bufs free
        // staging issue for g+2 into stg[(g+2)%3] (prior reader MMA(g-1) joined)
        if (g + 2 < total) cpaX(g + 2);
        asm volatile("cp.async.commit_group;" ::: "memory");
        // W issue for g+1 (prior reader MMA(g-1) of Wbuf[(g+1)&1] joined)
        if (tid == 0 && g + 1 < total) {
            int nti = (g + 1) / NST, ns2 = (g + 1) - nti * NST, nby = tiles[nti] & 1;
            uint32_t fb = mbF + ((g + 1) & 1) * 8;
            mb_tx(fb, WT);
            blkcp(sb + WB + ((g + 1) & 1) * WT, g_W + ((size_t)(nby * NST + ns2) << 15), WT, fb);
        }
        // MMA stage g: A via ldmatrix.trans from staging, B from Wbuf
        mb_wait(mbF + (g & 1) * 8, (g >> 1) & 1);
        {
            const uint32_t xg = sb + STG + (g % 3) * STGB;
            const uint32_t wb = sb + WB + (g & 1) * WT;
            #pragma unroll
            for (int ks = 0; ks < 4; ++ks) {
                uint32_t bf[8][2];
                const int browb = wn * 64 + (lane & 7) + ((lane >> 4) & 1) * 8;
                const int bc = 2 * ks + ((lane >> 3) & 1);
                #pragma unroll
                for (int np = 0; np < 4; ++np) {
                    int r = browb + np * 16;
                    uint32_t boff = r * 128 + ((bc ^ (r & 7)) << 4);
                    LDMX4(bf[np*2][0], bf[np*2][1], bf[np*2+1][0], bf[np*2+1][1], wb + boff);
                }
                const int kr = ks * 16 + (lane & 7) + ((lane >> 4) & 1) * 8;
                const int mcb = wm * 64 + ((lane >> 3) & 1) * 8;
                #pragma unroll
                for (int mt = 0; mt < 4; ++mt) {
                    uint32_t af[4];
                    uint32_t aaddr = xg + kr * 272 + (mcb + mt * 16) * 2;
                    LDMX4T(af[0], af[1], af[2], af[3], aaddr);
                    #pragma unroll
                    for (int nt = 0; nt < 8; ++nt)
                        MMA(acc[mt][nt], af, bf[nt]);
                }
            }
        }

        if (++s == NST) {
            // ---- epilogue for tile ti ----
            const int bx = tiles[ti] >> 1, by = tiles[ti] & 1;
            const int pos0 = bx * 128, a0 = by * 256, b = bx >> 3;
            __syncthreads();
            qs[tid] = g_query[b * At + a0 + tid];
            ws[tid] = Wv[a0 + tid];
            __syncthreads();
            #pragma unroll
            for (int mt = 0; mt < 4; ++mt) {
                float er0 = 0.f, er1 = 0.f;
                #pragma unroll
                for (int nt = 0; nt < 8; ++nt) {
                    int col = wn * 64 + nt * 8 + (lane & 3) * 2;
                    float q0 = qs[col], q1 = qs[col + 1];
                    float w0 = ws[col], w1 = ws[col + 1];
                    er0 = fmaf(w0, ftanh(acc[mt][nt][0] + q0), er0);
                    er0 = fmaf(w1, ftanh(acc[mt][nt][1] + q1), er0);
                    er1 = fmaf(w0, ftanh(acc[mt][nt][2] + q0), er1);
                    er1 = fmaf(w1, ftanh(acc[mt][nt][3] + q1), er1);
                }
                er0 += __shfl_xor_sync(0xffffffffu, er0, 1);
                er0 += __shfl_xor_sync(0xffffffffu, er0, 2);
                er1 += __shfl_xor_sync(0xffffffffu, er1, 1);
                er1 += __shfl_xor_sync(0xffffffffu, er1, 2);
                if ((lane & 3) == 0) {
                    int r = wm * 64 + mt * 16 + (lane >> 2);
                    esm[r * 4 + wn] = er0;
                    esm[(r + 8) * 4 + wn] = er1;
                }
            }
            __syncthreads();
            if (tid < 128)
                g_Epart[by * NPOS + pos0 + tid] =
                    esm[tid * 4] + esm[tid * 4 + 1] + esm[tid * 4 + 2] + esm[tid * 4 + 3];
            #pragma unroll
            for (int mt = 0; mt < 4; ++mt)
                #pragma unroll
                for (int nt = 0; nt < 8; ++nt)
                    #pragma unroll
                    for (int r = 0; r < 4; ++r) acc[mt][nt][r] = 0.f;
            s = 0; ++ti;
        }
    }

    // ==== all Epart written ====
    gridbar(0);

    // softmax per batch (CTAs 0-31); per-batch max (normalization-invariant)
    if (blockIdx.x < Bt) {
        const int b = blockIdx.x;
        float* exs = (float*)dsm;
        float bvv = bv[0];
        float ev[4], m = -1e30f;
        #pragma unroll
        for (int i = 0; i < 4; ++i) {
            int p = tid + i * 256;
            float e = bvv + g_Epart[b * HWt + p] + g_Epart[NPOS + b * HWt + p];
            ev[i] = e; m = fmaxf(m, e);
        }
        esm[tid] = m; __syncthreads();
        for (int s2 = 128; s2 > 0; s2 >>= 1) { if (tid < s2) esm[tid] = fmaxf(esm[tid], esm[tid + s2]); __syncthreads(); }
        m = esm[0];
        __syncthreads();
        float ls = 0.f;
        #pragma unroll
        for (int i = 0; i < 4; ++i) {
            int p = tid + i * 256;
            float v = expf(ev[i] - m) * mask[b * HWt + p];
            exs[p] = v; ls += v;
        }
        esm[tid] = ls; __syncthreads();
        for (int s2 = 128; s2 > 0; s2 >>= 1) { if (tid < s2) esm[tid] += esm[tid + s2]; __syncthreads(); }
        float inv = 1.f / (esm[0] + 1e-10f);
        #pragma unroll
        for (int i = 0; i < 4; ++i) {
            int p = tid + i * 256;
            float al = exs[p] * inv;
            out[ALPHA_OFF + b * HWt + p] = al;
            out[ASUM_OFF + b * HWt + p] = al + asum[b * HWt + p];
        }
    }

    gridbar(1);

    // context: full chip, 2 c-rows per block-iteration (alpha hot in L2)
    {
        const int cr = tid >> 7, l = tid & 127;
        const int wq = (tid >> 5) & 3;
        for (int idx = blockIdx.x; idx < (Ct / 2) * Bt; idx += NCTA) {
            int b = idx / (Ct / 2);
            int cp = idx - b * (Ct / 2);
            int c = cp * 2 + cr;
            const float4* f = (const float4*)(cnn + (size_t)(b * Ct + c) * HWt);
            const float4* al = (const float4*)(out + ALPHA_OFF + b * HWt);
            float sdot = 0.f;
            #pragma unroll
            for (int i = 0; i < 2; ++i) {
                float4 a4 = al[l + i * 128], f4 = f[l + i * 128];
                sdot += a4.x * f4.x + a4.y * f4.y + a4.z * f4.z + a4.w * f4.w;
            }
            #pragma unroll
            for (int o = 16; o > 0; o >>= 1) sdot += __shfl_xor_sync(0xffffffffu, sdot, o);
            if (lane == 0) esm[cr * 4 + wq] = sdot;
            BARS(3 + cr, 128);
            if (l == 0)
                out[b * Ct + c] = esm[cr * 4] + esm[cr * 4 + 1] + esm[cr * 4 + 2] + esm[cr * 4 + 3];
            BARS(3 + cr, 128);
        }
    }
}

// ---------------- launch ----------------
extern "C" void kernel_launch(void* const* d_in, const int* in_sizes, int n_in,
                              void* d_out, int out_size) {
    const float* cnn    = (const float*)d_in[0];
    const float* hidden = (const float*)d_in[1];
    const float* asum   = (const float*)d_in[2];
    const float* mask   = (const float*)d_in[3];
    const float* Wh     = (const float*)d_in[4];
    const float* bh     = (const float*)d_in[5];
    const float* Wec    = (const float*)d_in[6];
    const float* bec    = (const float*)d_in[7];
    const float* Wac    = (const float*)d_in[8];
    const float* Waw    = (const float*)d_in[9];
    const float* Wv     = (const float*)d_in[10];
    const float* bv     = (const float*)d_in[11];
    float* out = (float*)d_out;

    cudaFuncSetAttribute(k_mma, cudaFuncAttributeMaxDynamicSharedMemorySize, SMEM_SZ);

    k_small<<<dim3(At, 2), 128>>>(Waw, Wac, hidden, Wh, bh, bec);   // 1 (also zeroes counters)
    k_wpack<<<dim3(NST, 4), 256>>>(Wec);                            // 2
    k_xconv<<<dim3(21888, 2), 256>>>(cnn, asum);                    // 3
    k_mma<<<NCTA, 256, SMEM_SZ>>>(asum, mask, Wv, bv, cnn, out);    // 4 <- ncu slot
}